// round 1
// baseline (speedup 1.0000x reference)
#include <cuda_runtime.h>

#define SLICES 16
#define NCH 32            // 8 batches * {img,img_t} * {g,b}
#define NPIX 65536
#define NBIN 256

__device__ float g_hist[NCH][NBIN];
__device__ float g_cnt[NCH][NBIN];

__device__ __forceinline__ float frcp(float x) {
    float y; asm("rcp.approx.f32 %0, %1;" : "=f"(y) : "f"(x)); return y;
}

__global__ void zero_kernel() {
    g_hist[blockIdx.x][threadIdx.x] = 0.0f;
    g_cnt[blockIdx.x][threadIdx.x]  = 0.0f;
}

// e^{2.5 j} constants
#define E_M4 4.5399929762484854e-05f   // e^-10
#define E_M3 5.5308437014783363e-04f   // e^-7.5
#define E_M2 6.7379469990854670e-03f   // e^-5
#define E_M1 8.2084998623898800e-02f   // e^-2.5
#define E_P1 12.182493960703473f       // e^2.5
#define E_P2 148.41315910257660f       // e^5
#define E_P3 1808.0424144560632f       // e^7.5
#define Q_4  4.5399929762484854e-05f   // e^-10
#define Q_5  3.7266531720786709e-06f   // e^-12.5

__device__ __forceinline__ void process_pixel(float x, float* s_h, float* s_c) {
    float u = x * 255.0f;
    int k = (int)u;
    if (k > 254) k = 254;
    float f = u - (float)k;
    float e0 = __expf(-2.5f * f);      // in [e^-2.5, 1]
    float r0 = frcp(e0);               // e^{2.5 f}

    // count: contributes 1.0 to all thresholds i <= k-5 via suffix-sum later
    atomicAdd(&s_c[k], 1.0f);

    int i;
    // j = -4 (threshold k-4): sig = 1 - e_j, err < 2e-9
    i = k - 4; if (i >= 0) atomicAdd(&s_h[i], 1.0f - e0 * E_M4);
    // j = -3..3: exact sigmoid via rcp
    i = k - 3; if (i >= 0) atomicAdd(&s_h[i], frcp(1.0f + e0 * E_M3));
    i = k - 2; if (i >= 0) atomicAdd(&s_h[i], frcp(1.0f + e0 * E_M2));
    i = k - 1; if (i >= 0) atomicAdd(&s_h[i], frcp(1.0f + e0 * E_M1));
    atomicAdd(&s_h[k], frcp(1.0f + e0));
    // k <= 254 so k+1 <= 255 always valid
    atomicAdd(&s_h[k + 1], frcp(1.0f + e0 * E_P1));
    i = k + 2; if (i <= 255) atomicAdd(&s_h[i], frcp(1.0f + e0 * E_P2));
    i = k + 3; if (i <= 255) atomicAdd(&s_h[i], frcp(1.0f + e0 * E_P3));
    // j = 4,5: sig = q(1-q), q = e^{2.5(f-j)}, err < 2e-10
    i = k + 4; if (i <= 255) { float q = r0 * Q_4; atomicAdd(&s_h[i], q * (1.0f - q)); }
    i = k + 5; if (i <= 255) { float q = r0 * Q_5; atomicAdd(&s_h[i], q * (1.0f - q)); }
}

__global__ __launch_bounds__(256) void hist_kernel(const float* __restrict__ img,
                                                   const float* __restrict__ img_t) {
    __shared__ float s_h[NBIN];
    __shared__ float s_c[NBIN];
    int t = threadIdx.x;
    s_h[t] = 0.0f;
    s_c[t] = 0.0f;
    __syncthreads();

    int cidx = blockIdx.y;                 // 0..31
    int slice = blockIdx.x;                // 0..SLICES-1
    int b  = cidx >> 2;
    int im = (cidx >> 1) & 1;
    int ch = cidx & 1;                     // 0 -> g(plane 1), 1 -> b(plane 2)
    const float* src = im ? img_t : img;
    const float4* plane = (const float4*)(src + (size_t)(b * 3 + 1 + ch) * NPIX);

    // 4096 px per slice = 1024 float4; 256 threads -> 4 float4 each
    int base = slice * 1024;
    #pragma unroll
    for (int v = 0; v < 4; v++) {
        float4 p = plane[base + v * 256 + t];
        process_pixel(p.x, s_h, s_c);
        process_pixel(p.y, s_h, s_c);
        process_pixel(p.z, s_h, s_c);
        process_pixel(p.w, s_h, s_c);
    }
    __syncthreads();

    atomicAdd(&g_hist[cidx][t], s_h[t]);
    atomicAdd(&g_cnt[cidx][t],  s_c[t]);
}

__global__ __launch_bounds__(256) void reduce_kernel(float* __restrict__ out) {
    int b = blockIdx.x;         // batch 0..7
    int t = threadIdx.x;        // 0..255
    __shared__ float sc[4][NBIN];
    __shared__ float H[4][NBIN];
    __shared__ float red[NBIN];

    // channel order: gx, gy, bx, by
    int cid0 = b * 4 + 0, cid1 = b * 4 + 2, cid2 = b * 4 + 1, cid3 = b * 4 + 3;
    sc[0][t] = g_cnt[cid0][t]; H[0][t] = g_hist[cid0][t];
    sc[1][t] = g_cnt[cid1][t]; H[1][t] = g_hist[cid1][t];
    sc[2][t] = g_cnt[cid2][t]; H[2][t] = g_hist[cid2][t];
    sc[3][t] = g_cnt[cid3][t]; H[3][t] = g_hist[cid3][t];
    __syncthreads();

    // inclusive suffix scan of counts
    for (int s = 1; s < NBIN; s <<= 1) {
        float v0 = sc[0][t] + ((t + s < NBIN) ? sc[0][t + s] : 0.0f);
        float v1 = sc[1][t] + ((t + s < NBIN) ? sc[1][t + s] : 0.0f);
        float v2 = sc[2][t] + ((t + s < NBIN) ? sc[2][t + s] : 0.0f);
        float v3 = sc[3][t] + ((t + s < NBIN) ? sc[3][t + s] : 0.0f);
        __syncthreads();
        sc[0][t] = v0; sc[1][t] = v1; sc[2][t] = v2; sc[3][t] = v3;
        __syncthreads();
    }

    // H_total[i] = windowed + (# pixels with bin >= i+5)
    float add = (t + 5 < NBIN) ? 1.0f : 0.0f;  // selector computed per array below
    #pragma unroll
    for (int q = 0; q < 4; q++) {
        float suf = (t + 5 < NBIN) ? sc[q][t + 5] : 0.0f;
        H[q][t] = H[q][t] + suf;
    }
    (void)add;
    __syncthreads();

    float term = 0.0f;
    if (t < 255) {
        // cdf[J] = (H[0] - H[J+1]) / N ; J = t
        float dg = (H[0][0] - H[0][t + 1]) - (H[1][0] - H[1][t + 1]);
        float db = (H[2][0] - H[2][t + 1]) - (H[3][0] - H[3][t + 1]);
        term = dg * dg + db * db;
    }
    red[t] = term;
    __syncthreads();
    for (int s = 128; s > 0; s >>= 1) {
        if (t < s) red[t] += red[t + s];
        __syncthreads();
    }
    if (t == 0) out[b] = red[0] * (1.0f / (65536.0f * 65536.0f));
}

extern "C" void kernel_launch(void* const* d_in, const int* in_sizes, int n_in,
                              void* d_out, int out_size) {
    const float* img   = (const float*)d_in[0];
    const float* img_t = (const float*)d_in[1];
    float* out = (float*)d_out;

    zero_kernel<<<NCH, NBIN>>>();
    dim3 grid(SLICES, NCH);
    hist_kernel<<<grid, 256>>>(img, img_t);
    reduce_kernel<<<8, 256>>>(out);
}

// round 2
// speedup vs baseline: 1.4496x; 1.4496x over previous
#include <cuda_runtime.h>

#define SLICES 32
#define NCH 32            // 8 batches * {img,img_t} * {g,b}
#define NPIX 65536
#define NBIN 256

__device__ float g_ph[NCH][SLICES][NBIN];   // windowed partial hists
__device__ float g_pc[NCH][SLICES][NBIN];   // bin-count partials

__device__ __forceinline__ float frcp(float x) {
    float y; asm("rcp.approx.f32 %0, %1;" : "=f"(y) : "f"(x)); return y;
}

// e^{2.5 j} constants
#define E_M2 6.7379469990854670e-03f   // e^-5
#define E_M1 8.2084998623898800e-02f   // e^-2.5
#define E_P1 12.182493960703473f       // e^2.5
#define E_P2 148.41315910257660f       // e^5
#define Q_3  5.5308437014783363e-04f   // e^-7.5

__device__ __forceinline__ void process_pixel(float x, float* s_h, float* s_c) {
    float u = x * 255.0f;
    int k = (int)u;
    if (k > 254) k = 254;
    float f = u - (float)k;
    float e0 = __expf(-2.5f * f);      // e^{-2.5 f}, in [e^-2.5, 1]
    float r0 = frcp(e0);               // e^{+2.5 f}

    // count: later expanded to +1.0 on all thresholds i <= k-3 via suffix-sum
    atomicAdd(&s_c[k], 1.0f);

    int i;
    // j = -2: sig = 1/(1+a), a = e0*e^-5 <= 6.74e-3 -> 1 - a + a^2 (err < 3.1e-7)
    i = k - 2;
    if (i >= 0) {
        float a = e0 * E_M2;
        atomicAdd(&s_h[i], fmaf(a, a, -a) + 1.0f);
    }
    // j = -1, 0, +1, +2: exact sigmoid via rcp
    i = k - 1; if (i >= 0) atomicAdd(&s_h[i], frcp(1.0f + e0 * E_M1));
    atomicAdd(&s_h[k], frcp(1.0f + e0));
    atomicAdd(&s_h[k + 1], frcp(1.0f + e0 * E_P1));   // k+1 <= 255 always
    i = k + 2; if (i <= 255) atomicAdd(&s_h[i], frcp(1.0f + e0 * E_P2));
    // j = +3: q = e^{2.5(f-3)} <= 6.74e-3, sig = q - q^2 (err < 3.1e-7)
    i = k + 3;
    if (i <= 255) {
        float q = r0 * Q_3;
        atomicAdd(&s_h[i], fmaf(-q, q, q));
    }
}

__global__ __launch_bounds__(256) void hist_kernel(const float* __restrict__ img,
                                                   const float* __restrict__ img_t) {
    __shared__ float s_h[NBIN];
    __shared__ float s_c[NBIN];
    int t = threadIdx.x;
    s_h[t] = 0.0f;
    s_c[t] = 0.0f;
    __syncthreads();

    int cidx = blockIdx.y;                 // 0..31  (= b*4 + im*2 + ch)
    int slice = blockIdx.x;                // 0..SLICES-1
    int b  = cidx >> 2;
    int im = (cidx >> 1) & 1;
    int ch = cidx & 1;                     // 0 -> g(plane 1), 1 -> b(plane 2)
    const float* src = im ? img_t : img;
    const float4* plane = (const float4*)(src + (size_t)(b * 3 + 1 + ch) * NPIX);

    // 2048 px per slice = 512 float4; 256 threads -> 2 float4 each
    int base = slice * 512;
    #pragma unroll
    for (int v = 0; v < 2; v++) {
        float4 p = plane[base + v * 256 + t];
        process_pixel(p.x, s_h, s_c);
        process_pixel(p.y, s_h, s_c);
        process_pixel(p.z, s_h, s_c);
        process_pixel(p.w, s_h, s_c);
    }
    __syncthreads();

    g_ph[cidx][slice][t] = s_h[t];
    g_pc[cidx][slice][t] = s_c[t];
}

__global__ __launch_bounds__(256) void reduce_kernel(float* __restrict__ out) {
    int b = blockIdx.x;         // batch 0..7
    int t = threadIdx.x;        // 0..255
    __shared__ float sc[4][NBIN];
    __shared__ float H[4][NBIN];
    __shared__ float red[NBIN];

    // channel order: g_img, g_img_t, b_img, b_img_t
    int cid[4] = { b * 4 + 0, b * 4 + 2, b * 4 + 1, b * 4 + 3 };
    #pragma unroll
    for (int q = 0; q < 4; q++) {
        float hsum = 0.0f, csum = 0.0f;
        #pragma unroll
        for (int s = 0; s < SLICES; s++) {
            hsum += g_ph[cid[q]][s][t];
            csum += g_pc[cid[q]][s][t];
        }
        H[q][t] = hsum;
        sc[q][t] = csum;
    }
    __syncthreads();

    // inclusive suffix scan of counts
    for (int s = 1; s < NBIN; s <<= 1) {
        float v0 = sc[0][t] + ((t + s < NBIN) ? sc[0][t + s] : 0.0f);
        float v1 = sc[1][t] + ((t + s < NBIN) ? sc[1][t + s] : 0.0f);
        float v2 = sc[2][t] + ((t + s < NBIN) ? sc[2][t + s] : 0.0f);
        float v3 = sc[3][t] + ((t + s < NBIN) ? sc[3][t + s] : 0.0f);
        __syncthreads();
        sc[0][t] = v0; sc[1][t] = v1; sc[2][t] = v2; sc[3][t] = v3;
        __syncthreads();
    }

    // H_total[i] = windowed + (# pixels with bin >= i+3)
    #pragma unroll
    for (int q = 0; q < 4; q++) {
        float suf = (t + 3 < NBIN) ? sc[q][t + 3] : 0.0f;
        H[q][t] = H[q][t] + suf;
    }
    __syncthreads();

    float term = 0.0f;
    if (t < 255) {
        // cdf[J] = (H[0] - H[J+1]) / N ; J = t
        float dg = (H[0][0] - H[0][t + 1]) - (H[1][0] - H[1][t + 1]);
        float db = (H[2][0] - H[2][t + 1]) - (H[3][0] - H[3][t + 1]);
        term = dg * dg + db * db;
    }
    red[t] = term;
    __syncthreads();
    for (int s = 128; s > 0; s >>= 1) {
        if (t < s) red[t] += red[t + s];
        __syncthreads();
    }
    if (t == 0) out[b] = red[0] * (1.0f / (65536.0f * 65536.0f));
}

extern "C" void kernel_launch(void* const* d_in, const int* in_sizes, int n_in,
                              void* d_out, int out_size) {
    const float* img   = (const float*)d_in[0];
    const float* img_t = (const float*)d_in[1];
    float* out = (float*)d_out;

    dim3 grid(SLICES, NCH);
    hist_kernel<<<grid, 256>>>(img, img_t);
    reduce_kernel<<<8, 256>>>(out);
}